// round 1
// baseline (speedup 1.0000x reference)
#include <cuda_runtime.h>
#include <cstdint>

#define BB 4
#define NNODES 2048
#define DD 256
#define HH 8
#define HDIM 32
#define EE 65536
#define MASK_WORDS (NNODES / 32)   /* 64 */
#define MAXDEG 256

// ---------------- device scratch (no allocation allowed) ----------------
__device__ float g_Q[BB * NNODES * DD];
__device__ float g_K[BB * NNODES * DD];
__device__ float g_V[BB * NNODES * DD];
__device__ float g_att[BB * NNODES * DD];
__device__ unsigned int g_mask[NNODES * MASK_WORDS];

// ---------------- adjacency mask ----------------
__global__ void clear_mask_kernel() {
    int i = blockIdx.x * blockDim.x + threadIdx.x;
    if (i < NNODES * MASK_WORDS) g_mask[i] = 0u;
}

__global__ void build_mask_kernel(const int* __restrict__ edges) {
    int idx = blockIdx.x * blockDim.x + threadIdx.x;
    if (idx < EE) {
        int s = edges[idx];
        int d = edges[EE + idx];
        atomicOr(&g_mask[s * MASK_WORDS + (d >> 5)], 1u << (d & 31));
        atomicOr(&g_mask[d * MASK_WORDS + (s >> 5)], 1u << (s & 31));
    } else if (idx < EE + NNODES) {
        int i = idx - EE;
        atomicOr(&g_mask[i * MASK_WORDS + (i >> 5)], 1u << (i & 31));
    }
}

// ---------------- SGEMM: C[M,256] = A[M,256] @ W[256,256]^T + bias ----------------
// BM=128, BN=64, BK=16, 128 threads, 8x8 per-thread tile.
__device__ __forceinline__ void sgemm_body(const float* __restrict__ A,
                                           const float* __restrict__ W,
                                           const float* __restrict__ bias,
                                           float* __restrict__ C) {
    __shared__ float As[16][128];
    __shared__ float Ws[16][64];

    const int tid = threadIdx.x;
    const int m0 = blockIdx.x * 128;
    const int n0 = blockIdx.y * 64;
    const int tm = tid >> 3;   // 0..15
    const int tn = tid & 7;    // 0..7
    const int wrow = tid & 63;
    const int wk = (tid >> 6) * 8;

    float acc[8][8];
#pragma unroll
    for (int i = 0; i < 8; i++)
#pragma unroll
        for (int j = 0; j < 8; j++) acc[i][j] = 0.f;

    for (int k0 = 0; k0 < 256; k0 += 16) {
        const float4* Ar = reinterpret_cast<const float4*>(A + (size_t)(m0 + tid) * 256 + k0);
        float4 a0 = Ar[0], a1 = Ar[1], a2 = Ar[2], a3 = Ar[3];
        const float4* Wr = reinterpret_cast<const float4*>(W + (size_t)(n0 + wrow) * 256 + k0 + wk);
        float4 w0 = Wr[0], w1 = Wr[1];

        __syncthreads();   // protect smem from previous iteration's readers
        As[0][tid] = a0.x;  As[1][tid] = a0.y;  As[2][tid] = a0.z;  As[3][tid] = a0.w;
        As[4][tid] = a1.x;  As[5][tid] = a1.y;  As[6][tid] = a1.z;  As[7][tid] = a1.w;
        As[8][tid] = a2.x;  As[9][tid] = a2.y;  As[10][tid] = a2.z; As[11][tid] = a2.w;
        As[12][tid] = a3.x; As[13][tid] = a3.y; As[14][tid] = a3.z; As[15][tid] = a3.w;
        Ws[wk + 0][wrow] = w0.x; Ws[wk + 1][wrow] = w0.y;
        Ws[wk + 2][wrow] = w0.z; Ws[wk + 3][wrow] = w0.w;
        Ws[wk + 4][wrow] = w1.x; Ws[wk + 5][wrow] = w1.y;
        Ws[wk + 6][wrow] = w1.z; Ws[wk + 7][wrow] = w1.w;
        __syncthreads();

#pragma unroll
        for (int k = 0; k < 16; k++) {
            float4 aA = *reinterpret_cast<const float4*>(&As[k][tm * 8]);
            float4 aB = *reinterpret_cast<const float4*>(&As[k][tm * 8 + 4]);
            float4 bA = *reinterpret_cast<const float4*>(&Ws[k][tn * 8]);
            float4 bB = *reinterpret_cast<const float4*>(&Ws[k][tn * 8 + 4]);
            float a[8] = {aA.x, aA.y, aA.z, aA.w, aB.x, aB.y, aB.z, aB.w};
            float w[8] = {bA.x, bA.y, bA.z, bA.w, bB.x, bB.y, bB.z, bB.w};
#pragma unroll
            for (int i = 0; i < 8; i++)
#pragma unroll
                for (int j = 0; j < 8; j++) acc[i][j] += a[i] * w[j];
        }
    }

    float bs[8];
#pragma unroll
    for (int j = 0; j < 8; j++) bs[j] = bias[n0 + tn * 8 + j];

#pragma unroll
    for (int i = 0; i < 8; i++) {
        float* Cr = C + (size_t)(m0 + tm * 8 + i) * 256 + n0 + tn * 8;
        float4 o0, o1;
        o0.x = acc[i][0] + bs[0]; o0.y = acc[i][1] + bs[1];
        o0.z = acc[i][2] + bs[2]; o0.w = acc[i][3] + bs[3];
        o1.x = acc[i][4] + bs[4]; o1.y = acc[i][5] + bs[5];
        o1.z = acc[i][6] + bs[6]; o1.w = acc[i][7] + bs[7];
        reinterpret_cast<float4*>(Cr)[0] = o0;
        reinterpret_cast<float4*>(Cr)[1] = o1;
    }
}

__global__ void __launch_bounds__(128) qkv_kernel(const float* __restrict__ x,
                                                  const float* __restrict__ Wq, const float* __restrict__ bq,
                                                  const float* __restrict__ Wk, const float* __restrict__ bk,
                                                  const float* __restrict__ Wv, const float* __restrict__ bv) {
    const float* W; const float* bb; float* C;
    if (blockIdx.z == 0)      { W = Wq; bb = bq; C = g_Q; }
    else if (blockIdx.z == 1) { W = Wk; bb = bk; C = g_K; }
    else                      { W = Wv; bb = bv; C = g_V; }
    sgemm_body(x, W, bb, C);
}

__global__ void __launch_bounds__(128) oproj_kernel(const float* __restrict__ Wo,
                                                    const float* __restrict__ bo,
                                                    float* __restrict__ out) {
    sgemm_body(g_att, Wo, bo, out);
}

// ---------------- sparse masked attention ----------------
// One warp per (b, i); loops all 8 heads. Writes attended rows to g_att and
// the head-mean attention weights (sparse scatter) into attn_out.
__global__ void __launch_bounds__(128) attn_kernel(const float* __restrict__ tptr,
                                                   float* __restrict__ attn_out) {
    __shared__ int   s_idx[4][MAXDEG];
    __shared__ float s_sc[4][8][MAXDEG + 1];   // +1 pad: bank-conflict relief

    const int warp = threadIdx.x >> 5;
    const int lane = threadIdx.x & 31;
    const int flat = blockIdx.x * 4 + warp;          // 0 .. B*N-1
    const int b = flat >> 11;                        // / 2048
    const int i = flat & (NNODES - 1);
    const float invT = 1.0f / (*tptr);

    // --- enumerate neighbors from bitmask row i ---
    unsigned int w0 = g_mask[i * MASK_WORDS + lane];
    unsigned int w1 = g_mask[i * MASK_WORDS + 32 + lane];
    int c0 = __popc(w0), c1 = __popc(w1);

    int incl0 = c0;
#pragma unroll
    for (int d = 1; d < 32; d <<= 1) {
        int t = __shfl_up_sync(0xffffffffu, incl0, d);
        if (lane >= d) incl0 += t;
    }
    int tot0 = __shfl_sync(0xffffffffu, incl0, 31);
    int off0 = incl0 - c0;

    int incl1 = c1;
#pragma unroll
    for (int d = 1; d < 32; d <<= 1) {
        int t = __shfl_up_sync(0xffffffffu, incl1, d);
        if (lane >= d) incl1 += t;
    }
    int tot1 = __shfl_sync(0xffffffffu, incl1, 31);
    int off1 = tot0 + incl1 - c1;

    int deg = tot0 + tot1;
    if (deg > MAXDEG) deg = MAXDEG;   // unreachable for this input (max deg ~110)

    {
        int o = off0, base = lane * 32;
        while (w0) {
            int p = __ffs(w0) - 1; w0 &= w0 - 1;
            if (o < MAXDEG) s_idx[warp][o] = base + p;
            o++;
        }
        o = off1; base = 1024 + lane * 32;
        while (w1) {
            int p = __ffs(w1) - 1; w1 &= w1 - 1;
            if (o < MAXDEG) s_idx[warp][o] = base + p;
            o++;
        }
    }
    __syncwarp();

    // --- load q (lane g=lane&7 holds dim quarter g*4..g*4+3 of each head) ---
    const int g = lane & 7;
    const int nlane = lane >> 3;   // 0..3 : neighbor-within-chunk
    const float* Qrow = g_Q + (size_t)(b * NNODES + i) * DD;
    float4 q4[8];
#pragma unroll
    for (int h = 0; h < 8; h++)
        q4[h] = *reinterpret_cast<const float4*>(Qrow + h * 32 + g * 4);

    // --- pass 1: scores (4 neighbors per chunk, 8 lanes per neighbor) ---
#pragma unroll 1
    for (int h = 0; h < 8; h++) {
        float4 q = q4[h];
        for (int nb = 0; nb < deg; nb += 4) {
            int n = nb + nlane;
            int nc = (n < deg) ? n : (deg - 1);
            int j = s_idx[warp][nc];
            float4 k4 = *reinterpret_cast<const float4*>(
                g_K + (size_t)(b * NNODES + j) * DD + h * 32 + g * 4);
            float part = q.x * k4.x + q.y * k4.y + q.z * k4.z + q.w * k4.w;
            part += __shfl_xor_sync(0xffffffffu, part, 4);
            part += __shfl_xor_sync(0xffffffffu, part, 2);
            part += __shfl_xor_sync(0xffffffffu, part, 1);
            if (g == 0 && n < deg) s_sc[warp][h][n] = part * invT;
        }
    }
    __syncwarp();

    // --- softmax per head (lane group of 4 per head) ---
    {
        int hh = lane >> 2, sub = lane & 3;
        float m = -1e30f;
        for (int n = sub; n < deg; n += 4) m = fmaxf(m, s_sc[warp][hh][n]);
        m = fmaxf(m, __shfl_xor_sync(0xffffffffu, m, 1));
        m = fmaxf(m, __shfl_xor_sync(0xffffffffu, m, 2));
        float l = 0.f;
        for (int n = sub; n < deg; n += 4) {
            float p = __expf(s_sc[warp][hh][n] - m);
            s_sc[warp][hh][n] = p;
            l += p;
        }
        l += __shfl_xor_sync(0xffffffffu, l, 1);
        l += __shfl_xor_sync(0xffffffffu, l, 2);
        float inv_l = 1.0f / l;
        for (int n = sub; n < deg; n += 4) s_sc[warp][hh][n] *= inv_l;
    }
    __syncwarp();

    // --- pass 2: attended = attn @ V ; attn_mean scatter ---
    float acc[8];
#pragma unroll
    for (int h = 0; h < 8; h++) acc[h] = 0.f;

    float* arow = attn_out + ((size_t)b * NNODES + i) * NNODES;
    for (int n = 0; n < deg; n++) {
        int j = s_idx[warp][n];
        const float* Vr = g_V + (size_t)(b * NNODES + j) * DD;
        float psum = 0.f;
#pragma unroll
        for (int h = 0; h < 8; h++) {
            float p = s_sc[warp][h][n];   // uniform address -> broadcast
            psum += p;
            acc[h] += p * Vr[h * 32 + lane];
        }
        if (lane == 0) arow[j] = psum * 0.125f;
    }

    float* Ao = g_att + (size_t)(b * NNODES + i) * DD;
#pragma unroll
    for (int h = 0; h < 8; h++) Ao[h * 32 + lane] = acc[h];
}

// ---------------- launch ----------------
extern "C" void kernel_launch(void* const* d_in, const int* in_sizes, int n_in,
                              void* d_out, int out_size) {
    const float* x  = (const float*)d_in[0];
    const int* edges = (const int*)d_in[1];
    const float* Wq = (const float*)d_in[2];
    const float* bq = (const float*)d_in[3];
    const float* Wk = (const float*)d_in[4];
    const float* bk = (const float*)d_in[5];
    const float* Wv = (const float*)d_in[6];
    const float* bv = (const float*)d_in[7];
    const float* Wo = (const float*)d_in[8];
    const float* bo = (const float*)d_in[9];
    const float* temp = (const float*)d_in[10];

    float* out = (float*)d_out;
    float* attn_out = out + (size_t)BB * NNODES * DD;

    // zero the dense attn_mean output (sparse scatter fills the rest)
    cudaMemsetAsync(attn_out, 0, (size_t)BB * NNODES * NNODES * sizeof(float), 0);

    clear_mask_kernel<<<(NNODES * MASK_WORDS + 255) / 256, 256>>>();
    build_mask_kernel<<<(EE + NNODES + 255) / 256, 256>>>(edges);

    dim3 gqkv(BB * NNODES / 128, DD / 64, 3);
    qkv_kernel<<<gqkv, 128>>>(x, Wq, bq, Wk, bk, Wv, bv);

    attn_kernel<<<BB * NNODES / 4, 128>>>(temp, attn_out);

    dim3 go(BB * NNODES / 128, DD / 64, 1);
    oproj_kernel<<<go, 128>>>(Wo, bo, out);
}